// round 13
// baseline (speedup 1.0000x reference)
#include <cuda_runtime.h>
#include <cuda_fp16.h>
#include <math.h>
#include <stdint.h>

#define NROWS 65536
#define DIMS  64
#define KCODE 1024
#define BM    128
#define THREADS 256
#define NCHUNK 16           // 16 chunks of 64 codes
#define NBLK   (NROWS/BM)   // 512 row-blocks
#define GRID   296          // all-resident (148 SMs x occ 2); work-stealing
#define NPREP  260

// output layout (floats): [loss(1) | quantized(4194304) | perplexity(1) | encodings(67108864)]
#define Q_OFF    1
#define Q_SIZE   4194304
#define P_OFF    (Q_OFF + Q_SIZE)
#define ENC_OFF  (P_OFF + 1)

#define LDB   72            // padded fp16 row: 144B (conflict-free ldmatrix)
#define LDBB  144
#define IMGB  (KCODE * LDBB)      // 147456 per image
#define CHB   (64 * LDBB)         // 9216 per image per 64-code chunk
#define ESC   256.0f
#define NEG1S (-1.0f/256.0f)

// smem byte offsets
#define A_OFF    0                    // 2 images x 128 x 144 = 36864
#define B_OFF    36864                // 2 bufs x 18432 = 36864
#define BCHUNKB  18432
#define HE2_OFF  73728                // 1024 f32 (0.5*e2)
#define X2P_OFF  77824                // 256 f32 partials
#define X2_OFF   78848                // 128 f32 (loss only; also finalize scratch)
#define RMIN_OFF 79360
#define RIDX_OFF 79872
#define BLK_OFF  80384
#define SMEM_BYTES 80512

__device__ __half g_cbs[2 * KCODE * LDB];  // 2 padded split images (scaled x256)
__device__ float  g_he2[KCODE];            // 0.5 * ||e||^2
__device__ int    g_counts[KCODE];
__device__ double g_loss_sum;
__device__ int    g_blk;
__device__ int    g_prep_done;
__device__ int    g_done;

__device__ __forceinline__ uint32_t smem_u32(const void* p) {
    uint32_t a;
    asm("{ .reg .u64 t; cvta.to.shared.u64 t, %1; cvt.u32.u64 %0, t; }" : "=r"(a) : "l"(p));
    return a;
}
#define LDSM_X4(r0, r1, r2, r3, addr) \
    asm volatile("ldmatrix.sync.aligned.m8n8.x4.shared.b16 {%0,%1,%2,%3}, [%4];" \
                 : "=r"(r0), "=r"(r1), "=r"(r2), "=r"(r3) : "r"(addr))
#define MMA_F16(c0, c1, c2, c3, a0, a1, a2, a3, b0, b1) \
    asm volatile("mma.sync.aligned.m16n8k16.row.col.f32.f16.f16.f32 " \
                 "{%0,%1,%2,%3}, {%4,%5,%6,%7}, {%8,%9}, {%0,%1,%2,%3};" \
                 : "+f"(c0), "+f"(c1), "+f"(c2), "+f"(c3) \
                 : "r"(a0), "r"(a1), "r"(a2), "r"(a3), "r"(b0), "r"(b1))
#define CPA16(dst, src) \
    asm volatile("cp.async.cg.shared.global [%0], [%1], 16;" \
                 :: "r"((uint32_t)(dst)), "l"((unsigned long long)(src)) : "memory")
#define CPA_COMMIT() asm volatile("cp.async.commit_group;" ::: "memory")
#define CPA_WAIT0()  asm volatile("cp.async.wait_group 0;" ::: "memory")

// ---------------- single fused persistent kernel ----------------
__global__ __launch_bounds__(THREADS, 2)
void vq_kernel(const float* __restrict__ x,
               const float* __restrict__ cb,
               float* __restrict__ out) {
    extern __shared__ char smem[];
    const uint32_t su = smem_u32(smem);
    float* he2s = (float*)(smem + HE2_OFF);
    float* x2p  = (float*)(smem + X2P_OFF);
    float* x2s  = (float*)(smem + X2_OFF);
    float* rmin = (float*)(smem + RMIN_OFF);
    int*   ridx = (int*)(smem + RIDX_OFF);
    int*   sblk = (int*)(smem + BLK_OFF);
    int*   slast = (int*)(smem + BLK_OFF + 4);

    const int tid  = threadIdx.x;
    const int wid  = tid >> 5;
    const int lane = tid & 31;
    const int bid  = blockIdx.x;

    // ================= phase 0: distributed codebook prep =================
    if (bid < 256) {
        int idx = bid * 256 + tid;          // one element per thread
        int k = idx >> 6, c = idx & 63;
        float v = cb[idx];
        float vs = v * ESC;
        __half h = __float2half_rn(vs);
        float r1 = vs - __half2float(h);
        __half l = __float2half_rn(r1);
        g_cbs[k * LDB + c] = h;
        g_cbs[KCODE * LDB + k * LDB + c] = l;
        __threadfence();
        __syncthreads();
        if (tid == 0) atomicAdd(&g_prep_done, 1);
    } else if (bid < NPREP) {
        int k = (bid - 256) * 256 + tid;    // one code per thread
        float e2 = 0.f;
        #pragma unroll 8
        for (int c = 0; c < DIMS; c++) {
            float v = cb[k * DIMS + c];
            e2 = fmaf(v, v, e2);
        }
        g_he2[k] = 0.5f * e2;
        __threadfence();
        __syncthreads();
        if (tid == 0) atomicAdd(&g_prep_done, 1);
    }
    if (tid == 0) {
        while (atomicAdd(&g_prep_done, 0) < NPREP) __nanosleep(64);
    }
    __syncthreads();
    __threadfence();

    #pragma unroll
    for (int i = tid; i < KCODE; i += THREADS) he2s[i] = g_he2[i];

    // cp.async slot map: 1152 x 16B lines/chunk; 4 slots all threads, 5th iff tid<128
    const unsigned long long gb = (unsigned long long)__cvta_generic_to_global(g_cbs);
    unsigned long long cpa_src[5];
    uint32_t cpa_dst[5];
    const bool has5 = (tid < 128);
    #pragma unroll
    for (int u = 0; u < 5; u++) {
        int i = (u < 4) ? (tid + u * 256) : (1024 + tid);
        int q = i / 576, r = i % 576;
        cpa_dst[u] = (uint32_t)(q * CHB + r * 16);
        cpa_src[u] = gb + (unsigned long long)q * IMGB + (unsigned long long)r * 16;
    }

    const int bofs4 = (lane & 7) * LDBB + ((lane >> 3) & 1) * 16 + (lane >> 4) * 32;
    const int r0 = wid * 16 + (lane >> 2);
    const int r1 = r0 + 8;

    // ================= phase 1: persistent work-stealing main loop =================
    while (true) {
        __syncthreads();
        if (tid == 0) *sblk = atomicAdd(&g_blk, 1);
        __syncthreads();
        const int blk = *sblk;
        if (blk >= NBLK) break;

        const int n0  = blk * BM;
        const int b   = n0 >> 10;
        const int hw0 = n0 & 1023;
        const float* xb = x + (size_t)b * 65536 + hw0;

        // prefetch B chunk 0
        {
            uint32_t d0 = su + B_OFF;
            #pragma unroll
            for (int u = 0; u < 4; u++) CPA16(d0 + cpa_dst[u], cpa_src[u]);
            if (has5) CPA16(d0 + cpa_dst[4], cpa_src[4]);
            CPA_COMMIT();
        }

        // A setup: all 256 threads (2 per row, 32 dims each)
        {
            int r = tid & 127, half = tid >> 7;
            float xp = 0.f;
            #pragma unroll 8
            for (int cc = 0; cc < 32; cc++) {
                int c = half * 32 + cc;
                float v = xb[c * 1024 + r];
                xp = fmaf(v, v, xp);
                __half h = __float2half_rn(v);
                float rr1 = v - __half2float(h);
                __half l = __float2half_rn(rr1);
                *(__half*)(smem + A_OFF + 0 * 18432 + r * LDBB + c * 2) = h;
                *(__half*)(smem + A_OFF + 1 * 18432 + r * LDBB + c * 2) = l;
            }
            x2p[half * 128 + r] = xp;
        }
        __syncthreads();
        if (tid < BM) x2s[tid] = x2p[tid] + x2p[128 + tid];

        // A fragments: 2 images x 4 k-steps
        uint32_t af[2][4][4];
        {
            int row = wid * 16 + (lane & 15);
            int kh  = (lane >> 4) & 1;
            #pragma unroll
            for (int q = 0; q < 2; q++)
                #pragma unroll
                for (int ks = 0; ks < 4; ks++) {
                    uint32_t a = su + A_OFF + q * 18432 + row * LDBB + ks * 32 + kh * 16;
                    LDSM_X4(af[q][ks][0], af[q][ks][1], af[q][ks][2], af[q][ks][3], a);
                }
        }

        float best0 = 3.4e38f, best1 = 3.4e38f;
        int   bidx0 = 0,       bidx1 = 0;

        float* encb = out + ENC_OFF + (size_t)n0 * KCODE;
        float4* enc4 = (float4*)(encb + 2);
        if (tid == 0) *(float2*)encb = make_float2(0.f, 0.f);
        if (tid == 1) *(float2*)(encb + (size_t)BM * KCODE - 2) = make_float2(0.f, 0.f);

        for (int nt = 0; nt < NCHUNK; nt++) {
            CPA_WAIT0();
            __syncthreads();
            if (nt + 1 < NCHUNK) {
                uint32_t d0 = su + B_OFF + ((nt + 1) & 1) * BCHUNKB;
                unsigned long long so = (unsigned long long)(nt + 1) * CHB;
                #pragma unroll
                for (int u = 0; u < 4; u++) CPA16(d0 + cpa_dst[u], cpa_src[u] + so);
                if (has5) CPA16(d0 + cpa_dst[4], cpa_src[4] + so);
                CPA_COMMIT();
            }
            const uint32_t bufo = su + B_OFF + (nt & 1) * BCHUNKB;

            #pragma unroll
            for (int g = 0; g < 2; g++) {           // two 32-code groups per chunk
                float acc[4][4];
                #pragma unroll
                for (int t = 0; t < 4; t++)
                    #pragma unroll
                    for (int j = 0; j < 4; j++) acc[t][j] = 0.f;

                #pragma unroll
                for (int kp = 0; kp < 2; kp++) {
                    const int k0 = kp * 2, k1 = kp * 2 + 1;
                    #pragma unroll
                    for (int t = 0; t < 4; t++) {
                        const uint32_t tb = bufo + (g * 4 + t) * 8 * LDBB + kp * 64 + bofs4;
                        uint32_t bh[4], bl[4];
                        LDSM_X4(bh[0], bh[1], bh[2], bh[3], tb);
                        LDSM_X4(bl[0], bl[1], bl[2], bl[3], tb + CHB);
                        MMA_F16(acc[t][0],acc[t][1],acc[t][2],acc[t][3],
                                af[0][k0][0],af[0][k0][1],af[0][k0][2],af[0][k0][3],
                                bh[0],bh[1]);
                        MMA_F16(acc[t][0],acc[t][1],acc[t][2],acc[t][3],
                                af[0][k0][0],af[0][k0][1],af[0][k0][2],af[0][k0][3],
                                bl[0],bl[1]);
                        MMA_F16(acc[t][0],acc[t][1],acc[t][2],acc[t][3],
                                af[1][k0][0],af[1][k0][1],af[1][k0][2],af[1][k0][3],
                                bh[0],bh[1]);
                        MMA_F16(acc[t][0],acc[t][1],acc[t][2],acc[t][3],
                                af[0][k1][0],af[0][k1][1],af[0][k1][2],af[0][k1][3],
                                bh[2],bh[3]);
                        MMA_F16(acc[t][0],acc[t][1],acc[t][2],acc[t][3],
                                af[0][k1][0],af[0][k1][1],af[0][k1][2],af[0][k1][3],
                                bl[2],bl[3]);
                        MMA_F16(acc[t][0],acc[t][1],acc[t][2],acc[t][3],
                                af[1][k1][0],af[1][k1][1],af[1][k1][2],af[1][k1][3],
                                bh[2],bh[3]);
                    }
                }

                // epilogue: d_cmp = he2 - dot/256 (monotone in true distance)
                const int cb0 = nt * 64 + g * 32 + (lane & 3) * 2;
                float d0[8], d1[8];
                #pragma unroll
                for (int t = 0; t < 4; t++) {
                    float ha = he2s[cb0 + t * 8], hb = he2s[cb0 + t * 8 + 1];
                    d0[2*t]   = fmaf(NEG1S, acc[t][0], ha);
                    d0[2*t+1] = fmaf(NEG1S, acc[t][1], hb);
                    d1[2*t]   = fmaf(NEG1S, acc[t][2], ha);
                    d1[2*t+1] = fmaf(NEG1S, acc[t][3], hb);
                }
                float m0 = fminf(fminf(fminf(d0[0],d0[1]), fminf(d0[2],d0[3])),
                                 fminf(fminf(d0[4],d0[5]), fminf(d0[6],d0[7])));
                float m1 = fminf(fminf(fminf(d1[0],d1[1]), fminf(d1[2],d1[3])),
                                 fminf(fminf(d1[4],d1[5]), fminf(d1[6],d1[7])));
                if (m0 < best0) {           // strict < keeps lowest-index semantics
                    best0 = m0;
                    #pragma unroll
                    for (int j = 7; j >= 0; j--)
                        if (d0[j] == m0) bidx0 = cb0 + (j >> 1) * 8 + (j & 1);
                }
                if (m1 < best1) {
                    best1 = m1;
                    #pragma unroll
                    for (int j = 7; j >= 0; j--)
                        if (d1[j] == m1) bidx1 = cb0 + (j >> 1) * 8 + (j & 1);
                }

                // interleaved encodings zero-fill (slice = nt*2+g)
                #pragma unroll
                for (int u = 0; u < 4; u++) {
                    int i = (nt * 2 + g) * 1024 + u * 256 + tid;
                    if (i < 32767) enc4[i] = make_float4(0.f, 0.f, 0.f, 0.f);
                }
            }
        }

        // cross-lane argmin reduce (4 lanes per row), idx tie-break
        #pragma unroll
        for (int off = 1; off < 4; off <<= 1) {
            float ob0 = __shfl_xor_sync(0xffffffffu, best0, off);
            int   oi0 = __shfl_xor_sync(0xffffffffu, bidx0, off);
            if (ob0 < best0 || (ob0 == best0 && oi0 < bidx0)) { best0 = ob0; bidx0 = oi0; }
            float ob1 = __shfl_xor_sync(0xffffffffu, best1, off);
            int   oi1 = __shfl_xor_sync(0xffffffffu, bidx1, off);
            if (ob1 < best1 || (ob1 == best1 && oi1 < bidx1)) { best1 = ob1; bidx1 = oi1; }
        }
        if ((lane & 3) == 0) {
            rmin[r0] = fmaf(2.f, best0, x2s[r0]); ridx[r0] = bidx0;  // true min dist
            rmin[r1] = fmaf(2.f, best1, x2s[r1]); ridx[r1] = bidx1;
        }
        __syncthreads();

        if (tid < BM) atomicAdd(&g_counts[ridx[tid]], 1);

        if (tid < 32) {
            double s = (double)rmin[tid] + (double)rmin[tid + 32]
                     + (double)rmin[tid + 64] + (double)rmin[tid + 96];
            #pragma unroll
            for (int o = 16; o > 0; o >>= 1)
                s += __shfl_down_sync(0xffffffffu, s, o);
            if (tid == 0) atomicAdd(&g_loss_sum, s);
        }

        // quantized output (NCHW), coalesced over r
        float* qout = out + Q_OFF;
        #pragma unroll
        for (int i = 0; i < (BM * DIMS) / THREADS; i++) {
            int idx = tid + i * THREADS;
            int c = idx >> 7;
            int r = idx & 127;
            qout[(size_t)b * 65536 + (size_t)c * 1024 + hw0 + r] =
                cb[(size_t)ridx[r] * DIMS + c];
        }

        if (tid < BM)
            encb[(size_t)tid * KCODE + ridx[tid]] = 1.0f;
    }

    // ================= phase 2: last CTA finalizes + resets state =================
    __threadfence();
    if (tid == 0) {
        int d = atomicAdd(&g_done, 1);
        *slast = (d == GRID - 1) ? 1 : 0;
    }
    __syncthreads();
    if (*slast) {
        __threadfence();
        float* red = x2s;               // reuse smem scratch
        float acc = 0.f;
        #pragma unroll
        for (int i = 0; i < 4; i++) {
            int k = tid + i * 256;
            int c = g_counts[k];
            g_counts[k] = 0;
            float p = (float)c * (1.f / 65536.f);
            acc += p * logf(p + 1e-10f);
        }
        #pragma unroll
        for (int o = 16; o > 0; o >>= 1)
            acc += __shfl_down_sync(0xffffffffu, acc, o);
        if (lane == 0) red[wid] = acc;
        __syncthreads();
        if (tid == 0) {
            float s = 0.f;
            #pragma unroll
            for (int w = 0; w < 8; w++) s += red[w];
            out[P_OFF] = expf(-s);
            out[0]     = (float)(1.25 * g_loss_sum / 4194304.0);
            g_loss_sum   = 0.0;
            g_blk        = 0;
            g_done       = 0;
            g_prep_done  = 0;
        }
    }
}

extern "C" void kernel_launch(void* const* d_in, const int* in_sizes, int n_in,
                              void* d_out, int out_size) {
    const float* x  = (const float*)d_in[0];
    const float* cb = (const float*)d_in[1];
    float* out = (float*)d_out;

    cudaFuncSetAttribute(vq_kernel,
                         cudaFuncAttributeMaxDynamicSharedMemorySize, SMEM_BYTES);

    vq_kernel<<<GRID, THREADS, SMEM_BYTES>>>(x, cb, out);
}

// round 15
// speedup vs baseline: 1.0182x; 1.0182x over previous
#include <cuda_runtime.h>
#include <cuda_fp16.h>
#include <math.h>
#include <stdint.h>

#define NROWS 65536
#define DIMS  64
#define KCODE 1024
#define BM    128
#define THREADS 256
#define NCHUNK 32           // 32 chunks of 32 codes
#define CHW    32
#define NBLK   (NROWS/BM)   // 512 row-blocks
#define GRID   296          // all-resident (148 SMs x occ 2); work-stealing
#define NPREP  260

// output layout (floats): [loss(1) | quantized(4194304) | perplexity(1) | encodings(67108864)]
#define Q_OFF    1
#define Q_SIZE   4194304
#define P_OFF    (Q_OFF + Q_SIZE)
#define ENC_OFF  (P_OFF + 1)

#define LDB   72            // padded fp16 row: 144B (conflict-free ldmatrix)
#define LDBB  144
#define IMGB  (KCODE * LDBB)      // 147456 per image
#define CHB   4608                // bytes per image per 32-code chunk
#define ESC   256.0f
#define NEG1S (-1.0f/256.0f)

// smem byte offsets
#define A_OFF    0                    // 2 images x 128 x 144 = 36864
#define B_OFF    36864                // 2 bufs x 9216
#define BCHUNKB  9216
#define HE2_OFF  55296                // 1024 f32 (0.5*e2)
#define X2P_OFF  59392                // 256 f32 partials
#define X2_OFF   60416                // 128 f32
#define RMIN_OFF 60928
#define RIDX_OFF 61440
#define BLK_OFF  61952
#define SMEM_BYTES 62080

__device__ __half g_cbs[2 * KCODE * LDB];  // 2 padded split images (scaled x256)
__device__ float  g_he2[KCODE];            // 0.5 * ||e||^2
__device__ int    g_counts[KCODE];
__device__ double g_loss_sum;
__device__ int    g_blk;
__device__ int    g_prep_done;
__device__ int    g_done;

__device__ __forceinline__ uint32_t smem_u32(const void* p) {
    uint32_t a;
    asm("{ .reg .u64 t; cvta.to.shared.u64 t, %1; cvt.u32.u64 %0, t; }" : "=r"(a) : "l"(p));
    return a;
}
#define LDSM_X4(r0, r1, r2, r3, addr) \
    asm volatile("ldmatrix.sync.aligned.m8n8.x4.shared.b16 {%0,%1,%2,%3}, [%4];" \
                 : "=r"(r0), "=r"(r1), "=r"(r2), "=r"(r3) : "r"(addr))
#define MMA_F16(c0, c1, c2, c3, a0, a1, a2, a3, b0, b1) \
    asm volatile("mma.sync.aligned.m16n8k16.row.col.f32.f16.f16.f32 " \
                 "{%0,%1,%2,%3}, {%4,%5,%6,%7}, {%8,%9}, {%0,%1,%2,%3};" \
                 : "+f"(c0), "+f"(c1), "+f"(c2), "+f"(c3) \
                 : "r"(a0), "r"(a1), "r"(a2), "r"(a3), "r"(b0), "r"(b1))
#define CPA16(dst, src) \
    asm volatile("cp.async.cg.shared.global [%0], [%1], 16;" \
                 :: "r"((uint32_t)(dst)), "l"((unsigned long long)(src)) : "memory")
#define CPA_COMMIT() asm volatile("cp.async.commit_group;" ::: "memory")
#define CPA_WAIT0()  asm volatile("cp.async.wait_group 0;" ::: "memory")

// ---------------- single fused persistent kernel ----------------
__global__ __launch_bounds__(THREADS, 2)
void vq_kernel(const float* __restrict__ x,
               const float* __restrict__ cb,
               float* __restrict__ out) {
    extern __shared__ char smem[];
    const uint32_t su = smem_u32(smem);
    float* he2s = (float*)(smem + HE2_OFF);
    float* x2p  = (float*)(smem + X2P_OFF);
    float* x2s  = (float*)(smem + X2_OFF);
    float* rmin = (float*)(smem + RMIN_OFF);
    int*   ridx = (int*)(smem + RIDX_OFF);
    int*   sblk = (int*)(smem + BLK_OFF);
    int*   slast = (int*)(smem + BLK_OFF + 4);

    const int tid  = threadIdx.x;
    const int wid  = tid >> 5;
    const int lane = tid & 31;
    const int bid  = blockIdx.x;

    // ================= phase 0: distributed codebook prep =================
    if (bid < 256) {
        int idx = bid * 256 + tid;          // one element per thread
        int k = idx >> 6, c = idx & 63;
        float v = cb[idx];
        float vs = v * ESC;
        __half h = __float2half_rn(vs);
        float r1 = vs - __half2float(h);
        __half l = __float2half_rn(r1);
        g_cbs[k * LDB + c] = h;
        g_cbs[KCODE * LDB + k * LDB + c] = l;
        __threadfence();
        __syncthreads();
        if (tid == 0) atomicAdd(&g_prep_done, 1);
    } else if (bid < NPREP) {
        int k = (bid - 256) * 256 + tid;    // one code per thread
        float e2 = 0.f;
        #pragma unroll 8
        for (int c = 0; c < DIMS; c++) {
            float v = cb[k * DIMS + c];
            e2 = fmaf(v, v, e2);
        }
        g_he2[k] = 0.5f * e2;
        __threadfence();
        __syncthreads();
        if (tid == 0) atomicAdd(&g_prep_done, 1);
    }
    if (tid == 0) {
        while (atomicAdd(&g_prep_done, 0) < NPREP) __nanosleep(64);
    }
    __syncthreads();
    __threadfence();

    #pragma unroll
    for (int i = tid; i < KCODE; i += THREADS) he2s[i] = g_he2[i];

    // cp.async slot map: 576 x 16B lines/chunk; slots 0,1 all threads, slot 2 iff tid<64
    const unsigned long long gb = (unsigned long long)__cvta_generic_to_global(g_cbs);
    unsigned long long cpa_src[3];
    uint32_t cpa_dst[3];
    const bool has3 = (tid < 64);
    #pragma unroll
    for (int u = 0; u < 3; u++) {
        int i = tid + u * 256;
        int q = i / 288, r = i % 288;
        cpa_dst[u] = (uint32_t)(q * CHB + r * 16);
        cpa_src[u] = gb + (unsigned long long)q * IMGB + (unsigned long long)r * 16;
    }

    const int bofs4 = (lane & 7) * LDBB + ((lane >> 3) & 1) * 16 + (lane >> 4) * 32;
    const int r0 = wid * 16 + (lane >> 2);
    const int r1 = r0 + 8;

    // ================= phase 1: persistent work-stealing main loop =================
    while (true) {
        __syncthreads();
        if (tid == 0) *sblk = atomicAdd(&g_blk, 1);
        __syncthreads();
        const int blk = *sblk;
        if (blk >= NBLK) break;

        const int n0  = blk * BM;
        const int b   = n0 >> 10;
        const int hw0 = n0 & 1023;
        const float* xb = x + (size_t)b * 65536 + hw0;

        // prefetch B chunk 0
        {
            uint32_t d0 = su + B_OFF;
            CPA16(d0 + cpa_dst[0], cpa_src[0]);
            CPA16(d0 + cpa_dst[1], cpa_src[1]);
            if (has3) CPA16(d0 + cpa_dst[2], cpa_src[2]);
            CPA_COMMIT();
        }

        // A setup: all 256 threads (2 per row, 32 dims each)
        {
            int r = tid & 127, half = tid >> 7;
            float xp = 0.f;
            #pragma unroll 8
            for (int cc = 0; cc < 32; cc++) {
                int c = half * 32 + cc;
                float v = xb[c * 1024 + r];
                xp = fmaf(v, v, xp);
                __half h = __float2half_rn(v);
                float rr1 = v - __half2float(h);
                __half l = __float2half_rn(rr1);
                *(__half*)(smem + A_OFF + 0 * 18432 + r * LDBB + c * 2) = h;
                *(__half*)(smem + A_OFF + 1 * 18432 + r * LDBB + c * 2) = l;
            }
            x2p[half * 128 + r] = xp;
        }
        __syncthreads();
        if (tid < BM) x2s[tid] = x2p[tid] + x2p[128 + tid];

        // A fragments: 2 images x 4 k-steps
        uint32_t af[2][4][4];
        {
            int row = wid * 16 + (lane & 15);
            int kh  = (lane >> 4) & 1;
            #pragma unroll
            for (int q = 0; q < 2; q++)
                #pragma unroll
                for (int ks = 0; ks < 4; ks++) {
                    uint32_t a = su + A_OFF + q * 18432 + row * LDBB + ks * 32 + kh * 16;
                    LDSM_X4(af[q][ks][0], af[q][ks][1], af[q][ks][2], af[q][ks][3], a);
                }
        }

        float best0 = 3.4e38f, best1 = 3.4e38f;
        int   bidx0 = 0,       bidx1 = 0;

        float* encb = out + ENC_OFF + (size_t)n0 * KCODE;
        float4* enc4 = (float4*)(encb + 2);
        if (tid == 0) *(float2*)encb = make_float2(0.f, 0.f);
        if (tid == 1) *(float2*)(encb + (size_t)BM * KCODE - 2) = make_float2(0.f, 0.f);

        for (int nt = 0; nt < NCHUNK; nt++) {
            CPA_WAIT0();
            __syncthreads();
            if (nt + 1 < NCHUNK) {
                uint32_t d0 = su + B_OFF + ((nt + 1) & 1) * BCHUNKB;
                unsigned long long so = (unsigned long long)(nt + 1) * CHB;
                CPA16(d0 + cpa_dst[0], cpa_src[0] + so);
                CPA16(d0 + cpa_dst[1], cpa_src[1] + so);
                if (has3) CPA16(d0 + cpa_dst[2], cpa_src[2] + so);
                CPA_COMMIT();
            }
            const uint32_t bufo = su + B_OFF + (nt & 1) * BCHUNKB;

            float acc[4][4];
            #pragma unroll
            for (int t = 0; t < 4; t++)
                #pragma unroll
                for (int j = 0; j < 4; j++) acc[t][j] = 0.f;

            #pragma unroll
            for (int kp = 0; kp < 2; kp++) {        // ks pairs {0,1}, {2,3}
                const int k0 = kp * 2, k1 = kp * 2 + 1;
                // batch all B loads (latencies overlap), then interleave MMAs
                // across the 4 independent acc[t] chains (dep distance 4).
                uint32_t bh[4][4], bl[4][4];
                #pragma unroll
                for (int t = 0; t < 4; t++) {
                    const uint32_t tb = bufo + t * 8 * LDBB + kp * 64 + bofs4;
                    LDSM_X4(bh[t][0], bh[t][1], bh[t][2], bh[t][3], tb);
                    LDSM_X4(bl[t][0], bl[t][1], bl[t][2], bl[t][3], tb + CHB);
                }
                // round 1: hh @ k0   (per-acc order identical to R12/R13)
                #pragma unroll
                for (int t = 0; t < 4; t++)
                    MMA_F16(acc[t][0],acc[t][1],acc[t][2],acc[t][3],
                            af[0][k0][0],af[0][k0][1],af[0][k0][2],af[0][k0][3],
                            bh[t][0],bh[t][1]);
                // round 2: hl @ k0
                #pragma unroll
                for (int t = 0; t < 4; t++)
                    MMA_F16(acc[t][0],acc[t][1],acc[t][2],acc[t][3],
                            af[0][k0][0],af[0][k0][1],af[0][k0][2],af[0][k0][3],
                            bl[t][0],bl[t][1]);
                // round 3: lh @ k0
                #pragma unroll
                for (int t = 0; t < 4; t++)
                    MMA_F16(acc[t][0],acc[t][1],acc[t][2],acc[t][3],
                            af[1][k0][0],af[1][k0][1],af[1][k0][2],af[1][k0][3],
                            bh[t][0],bh[t][1]);
                // round 4: hh @ k1
                #pragma unroll
                for (int t = 0; t < 4; t++)
                    MMA_F16(acc[t][0],acc[t][1],acc[t][2],acc[t][3],
                            af[0][k1][0],af[0][k1][1],af[0][k1][2],af[0][k1][3],
                            bh[t][2],bh[t][3]);
                // round 5: hl @ k1
                #pragma unroll
                for (int t = 0; t < 4; t++)
                    MMA_F16(acc[t][0],acc[t][1],acc[t][2],acc[t][3],
                            af[0][k1][0],af[0][k1][1],af[0][k1][2],af[0][k1][3],
                            bl[t][2],bl[t][3]);
                // round 6: lh @ k1
                #pragma unroll
                for (int t = 0; t < 4; t++)
                    MMA_F16(acc[t][0],acc[t][1],acc[t][2],acc[t][3],
                            af[1][k1][0],af[1][k1][1],af[1][k1][2],af[1][k1][3],
                            bh[t][2],bh[t][3]);
            }

            // epilogue: d_cmp = he2 - dot/256 (monotone in true distance)
            const int cb0 = nt * CHW + (lane & 3) * 2;
            float d0[8], d1[8];
            #pragma unroll
            for (int t = 0; t < 4; t++) {
                float ha = he2s[cb0 + t * 8], hb = he2s[cb0 + t * 8 + 1];
                d0[2*t]   = fmaf(NEG1S, acc[t][0], ha);
                d0[2*t+1] = fmaf(NEG1S, acc[t][1], hb);
                d1[2*t]   = fmaf(NEG1S, acc[t][2], ha);
                d1[2*t+1] = fmaf(NEG1S, acc[t][3], hb);
            }
            float m0 = fminf(fminf(fminf(d0[0],d0[1]), fminf(d0[2],d0[3])),
                             fminf(fminf(d0[4],d0[5]), fminf(d0[6],d0[7])));
            float m1 = fminf(fminf(fminf(d1[0],d1[1]), fminf(d1[2],d1[3])),
                             fminf(fminf(d1[4],d1[5]), fminf(d1[6],d1[7])));
            if (m0 < best0) {           // strict < keeps lowest-index semantics
                best0 = m0;
                #pragma unroll
                for (int j = 7; j >= 0; j--)
                    if (d0[j] == m0) bidx0 = cb0 + (j >> 1) * 8 + (j & 1);
            }
            if (m1 < best1) {
                best1 = m1;
                #pragma unroll
                for (int j = 7; j >= 0; j--)
                    if (d1[j] == m1) bidx1 = cb0 + (j >> 1) * 8 + (j & 1);
            }

            // interleaved encodings zero-fill
            #pragma unroll
            for (int u = 0; u < 4; u++) {
                int i = nt * 1024 + u * 256 + tid;
                if (i < 32767) enc4[i] = make_float4(0.f, 0.f, 0.f, 0.f);
            }
        }

        // cross-lane argmin reduce (4 lanes per row), idx tie-break
        #pragma unroll
        for (int off = 1; off < 4; off <<= 1) {
            float ob0 = __shfl_xor_sync(0xffffffffu, best0, off);
            int   oi0 = __shfl_xor_sync(0xffffffffu, bidx0, off);
            if (ob0 < best0 || (ob0 == best0 && oi0 < bidx0)) { best0 = ob0; bidx0 = oi0; }
            float ob1 = __shfl_xor_sync(0xffffffffu, best1, off);
            int   oi1 = __shfl_xor_sync(0xffffffffu, bidx1, off);
            if (ob1 < best1 || (ob1 == best1 && oi1 < bidx1)) { best1 = ob1; bidx1 = oi1; }
        }
        if ((lane & 3) == 0) {
            rmin[r0] = fmaf(2.f, best0, x2s[r0]); ridx[r0] = bidx0;  // true min dist
            rmin[r1] = fmaf(2.f, best1, x2s[r1]); ridx[r1] = bidx1;
        }
        __syncthreads();

        if (tid < BM) atomicAdd(&g_counts[ridx[tid]], 1);

        if (tid < 32) {
            double s = (double)rmin[tid] + (double)rmin[tid + 32]
                     + (double)rmin[tid + 64] + (double)rmin[tid + 96];
            #pragma unroll
            for (int o = 16; o > 0; o >>= 1)
                s += __shfl_down_sync(0xffffffffu, s, o);
            if (tid == 0) atomicAdd(&g_loss_sum, s);
        }

        // quantized output (NCHW), coalesced over r
        float* qout = out + Q_OFF;
        #pragma unroll
        for (int i = 0; i < (BM * DIMS) / THREADS; i++) {
            int idx = tid + i * THREADS;
            int c = idx >> 7;
            int r = idx & 127;
            qout[(size_t)b * 65536 + (size_t)c * 1024 + hw0 + r] =
                cb[(size_t)ridx[r] * DIMS + c];
        }

        if (tid < BM)
            encb[(size_t)tid * KCODE + ridx[tid]] = 1.0f;
    }

    // ================= phase 2: last CTA finalizes + resets state =================
    __threadfence();
    if (tid == 0) {
        int d = atomicAdd(&g_done, 1);
        *slast = (d == GRID - 1) ? 1 : 0;
    }
    __syncthreads();
    if (*slast) {
        __threadfence();
        float* red = x2s;               // reuse smem scratch
        float acc = 0.f;
        #pragma unroll
        for (int i = 0; i < 4; i++) {
            int k = tid + i * 256;
            int c = g_counts[k];
            g_counts[k] = 0;
            float p = (float)c * (1.f / 65536.f);
            acc += p * logf(p + 1e-10f);
        }
        #pragma unroll
        for (int o = 16; o > 0; o >>= 1)
            acc += __shfl_down_sync(0xffffffffu, acc, o);
        if (lane == 0) red[wid] = acc;
        __syncthreads();
        if (tid == 0) {
            float s = 0.f;
            #pragma unroll
            for (int w = 0; w < 8; w++) s += red[w];
            out[P_OFF] = expf(-s);
            out[0]     = (float)(1.25 * g_loss_sum / 4194304.0);
            g_loss_sum   = 0.0;
            g_blk        = 0;
            g_done       = 0;
            g_prep_done  = 0;
        }
    }
}

extern "C" void kernel_launch(void* const* d_in, const int* in_sizes, int n_in,
                              void* d_out, int out_size) {
    const float* x  = (const float*)d_in[0];
    const float* cb = (const float*)d_in[1];
    float* out = (float*)d_out;

    cudaFuncSetAttribute(vq_kernel,
                         cudaFuncAttributeMaxDynamicSharedMemorySize, SMEM_BYTES);

    vq_kernel<<<GRID, THREADS, SMEM_BYTES>>>(x, cb, out);
}